// round 9
// baseline (speedup 1.0000x reference)
#include <cuda_runtime.h>
#include <cstdint>
#include <cstddef>

#define IN_F    4096
#define OUT_F   4096
#define BATCHSZ 16384
// stage1 per kb: M=16384, N=192, K=1024 ; stage2 per lb: M=16384, N=1024 (4x256), K=192

// Split bf16 operand planes, pair-packed along k (low k in low 16 bits).
__device__ uint32_t g_w1h[4 * 192 * 512];          // w1 hi plane  [kb][q][512 pairs]
__device__ uint32_t g_w1l[4 * 192 * 512];          // w1 lo plane
__device__ uint32_t g_w2h[4 * 1024 * 96];          // w2 hi plane  [lb][s][96 pairs]
__device__ uint32_t g_w2l[4 * 1024 * 96];
__device__ uint32_t g_scr_h[(size_t)BATCHSZ * 4 * 96];   // stage1 out hi plane
__device__ uint32_t g_scr_l[(size_t)BATCHSZ * 4 * 96];   // stage1 out lo plane

#define PSTR 20   // padded row stride in u32 pair-words (16B aligned, conflict-free)

__device__ __forceinline__ uint32_t smem_u32(const void* p) {
    uint32_t a;
    asm("{ .reg .u64 t; cvta.to.shared.u64 t, %1; cvt.u32.u64 %0, t; }" : "=r"(a) : "l"(p));
    return a;
}
// pack two floats as bf16x2: 'lo' -> bits[15:0], 'hi' -> bits[31:16]
__device__ __forceinline__ uint32_t pack_bf2(float lo, float hi) {
    uint32_t r; asm("cvt.rn.bf16x2.f32 %0, %1, %2;" : "=r"(r) : "f"(hi), "f"(lo)); return r;
}
__device__ __forceinline__ float bf_lo(uint32_t u) { return __uint_as_float(u << 16); }
__device__ __forceinline__ float bf_hi(uint32_t u) { return __uint_as_float(u & 0xFFFF0000u); }

#define CP16(dst, src) asm volatile("cp.async.cg.shared.global [%0], [%1], 16;" :: "r"(dst), "l"(src))
#define CPCOMMIT()     asm volatile("cp.async.commit_group;" ::: "memory")
#define CPWAIT(n)      asm volatile("cp.async.wait_group %0;" :: "n"(n) : "memory")

__device__ __forceinline__ void mma_bf16(float c[4], const uint32_t a[4], const uint32_t b[2]) {
    asm volatile(
        "mma.sync.aligned.m16n8k16.row.col.f32.bf16.bf16.f32 "
        "{%0,%1,%2,%3}, {%4,%5,%6,%7}, {%8,%9}, {%0,%1,%2,%3};"
        : "+f"(c[0]), "+f"(c[1]), "+f"(c[2]), "+f"(c[3])
        : "r"(a[0]), "r"(a[1]), "r"(a[2]), "r"(a[3]), "r"(b[0]), "r"(b[1]));
}

// ------------------------------------------------------------- prep: split weights
__global__ void prep_kernel(const float* __restrict__ w1, const float* __restrict__ w2) {
    const int np = 4 * 192 * 512;   // pairs per matrix (== 4*1024*96)
    for (int j = blockIdx.x * blockDim.x + threadIdx.x; j < np; j += gridDim.x * blockDim.x) {
        {
            float2 v = *(const float2*)(w1 + 2 * (size_t)j);
            uint32_t h = pack_bf2(v.x, v.y);
            uint32_t l = pack_bf2(v.x - bf_lo(h), v.y - bf_hi(h));
            g_w1h[j] = h; g_w1l[j] = l;
        }
        {
            float2 v = *(const float2*)(w2 + 2 * (size_t)j);
            uint32_t h = pack_bf2(v.x, v.y);
            uint32_t l = pack_bf2(v.x - bf_lo(h), v.y - bf_hi(h));
            g_w2h[j] = h; g_w2l[j] = l;
        }
    }
}

// ---------------------------------------------------------------------------
// Stage 1: CTA 64x192, K=1024 (32 chunks of 32 = 16 pairs). 256 thr, 8 warps
// = 2m x 4n, warp tile 32x48. x split in-register; 3-term bf16 MMA.
// Per stage (u32): Ah 64*20=1280, Al 1280, Bh 192*20=3840, Bl 3840 -> 10240
// ---------------------------------------------------------------------------
#define S1_STW   10240
#define S1_SMEM  (3 * S1_STW * 4)    // 122880 B

__global__ void __launch_bounds__(256, 1)
s1_kernel(const float* __restrict__ x)
{
    extern __shared__ uint32_t smu[];
    const uint32_t sb = smem_u32(smu);
    const int tid = threadIdx.x, wid = tid >> 5, lane = tid & 31;
    const int wm = wid >> 2, wn = wid & 3;       // 2 x 4
    const int lr = lane >> 2, lc = lane & 3;
    const int mblk = blockIdx.x, kb = blockIdx.y;
    const size_t m0 = (size_t)mblk * 64;

    const float* xA = x + m0 * IN_F + (size_t)kb * 1024;
    const uint32_t* wBh = g_w1h + (size_t)kb * 192 * 512;
    const uint32_t* wBl = g_w1l + (size_t)kb * 192 * 512;

    float4 ra[2];
    auto ldgA = [&](int kc) {
#pragma unroll
        for (int i = 0; i < 2; i++) {
            int idx = i * 256 + tid, row = idx >> 3, c4 = idx & 7;
            ra[i] = *(const float4*)(xA + (size_t)row * IN_F + kc * 32 + c4 * 4);
        }
    };
    auto stsA = [&](int s) {
        const uint32_t ah = sb + (uint32_t)(s * S1_STW) * 4;
        const uint32_t al = ah + 1280 * 4;
#pragma unroll
        for (int i = 0; i < 2; i++) {
            int idx = i * 256 + tid, row = idx >> 3, c4 = idx & 7;
            float4 v = ra[i];
            uint32_t h0 = pack_bf2(v.x, v.y), h1 = pack_bf2(v.z, v.w);
            uint32_t l0 = pack_bf2(v.x - bf_lo(h0), v.y - bf_hi(h0));
            uint32_t l1 = pack_bf2(v.z - bf_lo(h1), v.w - bf_hi(h1));
            uint32_t off = (uint32_t)(row * PSTR + c4 * 2) * 4;
            asm volatile("st.shared.v2.b32 [%0], {%1,%2};" :: "r"(ah + off), "r"(h0), "r"(h1));
            asm volatile("st.shared.v2.b32 [%0], {%1,%2};" :: "r"(al + off), "r"(l0), "r"(l1));
        }
    };
    auto cpB = [&](int kc, int s) {
        const uint32_t bh = sb + (uint32_t)(s * S1_STW + 2560) * 4;
        const uint32_t bl = bh + 3840 * 4;
#pragma unroll
        for (int i = 0; i < 3; i++) {   // hi plane: 192 rows x 4 x16B
            int idx = i * 256 + tid, row = idx >> 2, q4 = idx & 3;
            CP16(bh + (uint32_t)(row * PSTR + q4 * 4) * 4, wBh + (size_t)row * 512 + kc * 16 + q4 * 4);
        }
#pragma unroll
        for (int i = 0; i < 3; i++) {   // lo plane
            int idx = i * 256 + tid, row = idx >> 2, q4 = idx & 3;
            CP16(bl + (uint32_t)(row * PSTR + q4 * 4) * 4, wBl + (size_t)row * 512 + kc * 16 + q4 * 4);
        }
        CPCOMMIT();
    };

    float c[2][6][4];
#pragma unroll
    for (int mi = 0; mi < 2; mi++)
#pragma unroll
        for (int ni = 0; ni < 6; ni++)
#pragma unroll
            for (int e = 0; e < 4; e++) c[mi][ni][e] = 0.f;

    // prologue
    ldgA(0); stsA(0); cpB(0, 0);
    ldgA(1); stsA(1); cpB(1, 1);
    ldgA(2);

#pragma unroll 1
    for (int kc = 0; kc < 32; kc++) {
        if (kc < 31) { CPWAIT(1); } else { CPWAIT(0); }
        __syncthreads();
        if (kc + 2 < 32) {
            stsA((kc + 2) % 3);               // ra holds chunk kc+2
            if (kc + 3 < 32) ldgA(kc + 3);
            cpB(kc + 2, (kc + 2) % 3);
        }

        const uint32_t* Ah = smu + (kc % 3) * S1_STW;
        const uint32_t* Al = Ah + 1280;
        const uint32_t* Bh = smu + (kc % 3) * S1_STW + 2560;
        const uint32_t* Bl = Bh + 3840;
#pragma unroll
        for (int kk = 0; kk < 2; kk++) {
            const int pc = kk * 8 + lc;
            uint32_t ah[2][4], al[2][4], bh[6][2], bl[6][2];
#pragma unroll
            for (int mi = 0; mi < 2; mi++) {
                int r = wm * 32 + mi * 16 + lr;
                ah[mi][0] = Ah[r * PSTR + pc];       al[mi][0] = Al[r * PSTR + pc];
                ah[mi][1] = Ah[(r + 8) * PSTR + pc]; al[mi][1] = Al[(r + 8) * PSTR + pc];
                ah[mi][2] = Ah[r * PSTR + pc + 4];   al[mi][2] = Al[r * PSTR + pc + 4];
                ah[mi][3] = Ah[(r + 8) * PSTR + pc + 4]; al[mi][3] = Al[(r + 8) * PSTR + pc + 4];
            }
#pragma unroll
            for (int ni = 0; ni < 6; ni++) {
                int n = wn * 48 + ni * 8 + lr;
                bh[ni][0] = Bh[n * PSTR + pc]; bh[ni][1] = Bh[n * PSTR + pc + 4];
                bl[ni][0] = Bl[n * PSTR + pc]; bl[ni][1] = Bl[n * PSTR + pc + 4];
            }
#pragma unroll
            for (int mi = 0; mi < 2; mi++)
#pragma unroll
                for (int ni = 0; ni < 6; ni++) {
                    mma_bf16(c[mi][ni], ah[mi], bh[ni]);
                    mma_bf16(c[mi][ni], ah[mi], bl[ni]);
                    mma_bf16(c[mi][ni], al[mi], bh[ni]);
                }
        }
    }

    // Epilogue: split result into bf16 h/l pair planes, fused block transpose.
    // warp's 48-col span == one l block (l = wn); cols (q, q+1) adjacent.
#pragma unroll
    for (int mi = 0; mi < 2; mi++) {
#pragma unroll
        for (int half = 0; half < 2; half++) {
            int row = (int)m0 + wm * 32 + mi * 16 + half * 8 + lr;
            size_t base = ((size_t)row * 4 + wn) * 96 + kb * 24 + lc;
#pragma unroll
            for (int ni = 0; ni < 6; ni++) {
                float v0 = c[mi][ni][half * 2 + 0];
                float v1 = c[mi][ni][half * 2 + 1];
                uint32_t h = pack_bf2(v0, v1);
                uint32_t l = pack_bf2(v0 - bf_lo(h), v1 - bf_hi(h));
                g_scr_h[base + ni * 4] = h;
                g_scr_l[base + ni * 4] = l;
            }
        }
    }
}

// ---------------------------------------------------------------------------
// Stage 2: CTA 128x256, K=192 (6 chunks of 32 = 16 pairs). 256 thr, 8 warps
// = 2m x 4n, warp tile 64x64. Pure cp.async; 3-term bf16 MMA; bias fused.
// Per stage (u32): Ah 128*20=2560, Al 2560, Bh 256*20=5120, Bl 5120 -> 15360
// ---------------------------------------------------------------------------
#define S2_STW   15360
#define S2_SMEM  (3 * S2_STW * 4)    // 184320 B

__global__ void __launch_bounds__(256, 1)
s2_kernel(const float* __restrict__ bias, float* __restrict__ out)
{
    extern __shared__ uint32_t smu[];
    const uint32_t sb = smem_u32(smu);
    const int tid = threadIdx.x, wid = tid >> 5, lane = tid & 31;
    const int wm = wid >> 2, wn = wid & 3;       // 2 x 4
    const int lr = lane >> 2, lc = lane & 3;
    const int nblk = blockIdx.x, mblk = blockIdx.y, lb = blockIdx.z;
    const size_t m0 = (size_t)mblk * 128;

    const uint32_t* Agh = g_scr_h + (m0 * 4 + lb) * 96;
    const uint32_t* Agl = g_scr_l + (m0 * 4 + lb) * 96;
    const uint32_t* Bgh = g_w2h + ((size_t)lb * 1024 + (size_t)nblk * 256) * 96;
    const uint32_t* Bgl = g_w2l + ((size_t)lb * 1024 + (size_t)nblk * 256) * 96;

    auto cpA = [&](int kc, int s) {
        const uint32_t ah = sb + (uint32_t)(s * S2_STW) * 4;
        const uint32_t al = ah + 2560 * 4;
#pragma unroll
        for (int i = 0; i < 2; i++) {   // hi: 128 rows x 4 x16B
            int idx = i * 256 + tid, row = idx >> 2, q4 = idx & 3;
            CP16(ah + (uint32_t)(row * PSTR + q4 * 4) * 4, Agh + (size_t)row * 384 + kc * 16 + q4 * 4);
        }
#pragma unroll
        for (int i = 0; i < 2; i++) {   // lo
            int idx = i * 256 + tid, row = idx >> 2, q4 = idx & 3;
            CP16(al + (uint32_t)(row * PSTR + q4 * 4) * 4, Agl + (size_t)row * 384 + kc * 16 + q4 * 4);
        }
    };
    auto cpB = [&](int kc, int s) {
        const uint32_t bh = sb + (uint32_t)(s * S2_STW + 5120) * 4;
        const uint32_t bl = bh + 5120 * 4;
#pragma unroll
        for (int i = 0; i < 4; i++) {   // hi: 256 rows x 4 x16B
            int idx = i * 256 + tid, row = idx >> 2, q4 = idx & 3;
            CP16(bh + (uint32_t)(row * PSTR + q4 * 4) * 4, Bgh + (size_t)row * 96 + kc * 16 + q4 * 4);
        }
#pragma unroll
        for (int i = 0; i < 4; i++) {   // lo
            int idx = i * 256 + tid, row = idx >> 2, q4 = idx & 3;
            CP16(bl + (uint32_t)(row * PSTR + q4 * 4) * 4, Bgl + (size_t)row * 96 + kc * 16 + q4 * 4);
        }
        CPCOMMIT();
    };

    float c[4][8][4];
#pragma unroll
    for (int mi = 0; mi < 4; mi++)
#pragma unroll
        for (int ni = 0; ni < 8; ni++)
#pragma unroll
            for (int e = 0; e < 4; e++) c[mi][ni][e] = 0.f;

    cpA(0, 0); cpB(0, 0);
    cpA(1, 1); cpB(1, 1);

#pragma unroll 1
    for (int kc = 0; kc < 6; kc++) {
        if (kc < 5) { CPWAIT(1); } else { CPWAIT(0); }
        __syncthreads();
        if (kc + 2 < 6) { cpA(kc + 2, (kc + 2) % 3); cpB(kc + 2, (kc + 2) % 3); }

        const uint32_t* Ah = smu + (kc % 3) * S2_STW;
        const uint32_t* Al = Ah + 2560;
        const uint32_t* Bh = smu + (kc % 3) * S2_STW + 5120;
        const uint32_t* Bl = Bh + 5120;
#pragma unroll
        for (int kk = 0; kk < 2; kk++) {
            const int pc = kk * 8 + lc;
            uint32_t ah[4][4], al[4][4], bh[8][2], bl[8][2];
#pragma unroll
            for (int mi = 0; mi < 4; mi++) {
                int r = wm * 64 + mi * 16 + lr;
                ah[mi][0] = Ah[r * PSTR + pc];       al[mi][0] = Al[r * PSTR + pc];
                ah[mi][1] = Ah[(r + 8) * PSTR + pc]; al[mi][1] = Al[(r + 8) * PSTR + pc];
                ah[mi][2] = Ah[r * PSTR + pc + 4];   al[mi][2] = Al[r * PSTR + pc + 4];
                ah[mi][3] = Ah[(r + 8) * PSTR + pc + 4]; al[mi][3] = Al[(r + 8) * PSTR + pc + 4];
            }
#pragma unroll
            for (int ni = 0; ni < 8; ni++) {
                int n = wn * 64 + ni * 8 + lr;
                bh[ni][0] = Bh[n * PSTR + pc]; bh[ni][1] = Bh[n * PSTR + pc + 4];
                bl[ni][0] = Bl[n * PSTR + pc]; bl[ni][1] = Bl[n * PSTR + pc + 4];
            }
#pragma unroll
            for (int mi = 0; mi < 4; mi++)
#pragma unroll
                for (int ni = 0; ni < 8; ni++) {
                    mma_bf16(c[mi][ni], ah[mi], bh[ni]);
                    mma_bf16(c[mi][ni], ah[mi], bl[ni]);
                    mma_bf16(c[mi][ni], al[mi], bh[ni]);
                }
        }
    }

    // Epilogue: bias preload, float2 writes per row.
    const int col0 = lb * 1024 + nblk * 256 + wn * 64 + 2 * lc;
    float2 bs[8];
#pragma unroll
    for (int ni = 0; ni < 8; ni++)
        bs[ni] = *(const float2*)(bias + col0 + ni * 8);

#pragma unroll
    for (int mi = 0; mi < 4; mi++) {
        int row0 = wm * 64 + mi * 16 + lr;
        float* o0 = out + (m0 + row0) * OUT_F + col0;
#pragma unroll
        for (int ni = 0; ni < 8; ni++) {
            float2 v0 = {c[mi][ni][0] + bs[ni].x, c[mi][ni][1] + bs[ni].y};
            float2 v1 = {c[mi][ni][2] + bs[ni].x, c[mi][ni][3] + bs[ni].y};
            *(float2*)(o0 + ni * 8) = v0;
            *(float2*)(o0 + ni * 8 + (size_t)8 * OUT_F) = v1;
        }
    }
}

// ---------------------------------------------------------------------------
extern "C" void kernel_launch(void* const* d_in, const int* in_sizes, int n_in,
                              void* d_out, int out_size)
{
    const float* x    = (const float*)d_in[0];
    const float* w1   = (const float*)d_in[1];
    const float* w2   = (const float*)d_in[2];
    const float* bias = (const float*)d_in[3];
    float* out = (float*)d_out;

    cudaFuncSetAttribute(s1_kernel, cudaFuncAttributeMaxDynamicSharedMemorySize, S1_SMEM);
    cudaFuncSetAttribute(s2_kernel, cudaFuncAttributeMaxDynamicSharedMemorySize, S2_SMEM);

    prep_kernel<<<384, 256>>>(w1, w2);
    // mblk fastest: per-kb / per-(lb,nblk) weight slices stay L2-hot across the m-sweep
    s1_kernel<<<dim3(256, 4), 256, S1_SMEM>>>(x);
    s2_kernel<<<dim3(4, 128, 4), 256, S2_SMEM>>>(bias, out);
}

// round 10
// speedup vs baseline: 1.3835x; 1.3835x over previous
#include <cuda_runtime.h>
#include <cstdint>
#include <cstddef>

#define IN_F    4096
#define OUT_F   4096
#define BATCHSZ 16384
// stage1 tile: 64x192xK1024 per (mblk64, kb)  -> 256*4 = 1024 tiles
// stage2 tile: 128x256xK192 per (nblk, lb, mblk128) -> 4*4*128 = 2048 tiles

// scratch[(b*4 + l)*192 + kb*48 + b1], tf32-rounded fp32 (low 13 bits zero)
__device__ float g_scratch[(size_t)BATCHSZ * 4 * 192];
__device__ float g_w1r[4 * 192 * 1024];   // rna(tf32)-rounded weights
__device__ float g_w2r[4 * 1024 * 192];
__device__ int   g_ctr;                   // persistent tile queue
__device__ int   g_flags[256];            // per-mblk64: #kb tiles complete (0..4)

#define SSTR 36   // padded row stride in 4B words (conflict-free, 16B aligned)

#define S1_TILES 1024
#define TOT_TILES (1024 + 2048)

__device__ __forceinline__ uint32_t f2tf32(float f) {
    uint32_t r; asm("cvt.rna.tf32.f32 %0, %1;" : "=r"(r) : "f"(f)); return r;
}
#define CP16(dst, src) asm volatile("cp.async.cg.shared.global [%0], [%1], 16;" :: "r"(dst), "l"(src))
#define CPCOMMIT()     asm volatile("cp.async.commit_group;" ::: "memory")
#define CPWAIT(n)      asm volatile("cp.async.wait_group %0;" :: "n"(n) : "memory")

__device__ __forceinline__ uint32_t smem_u32(const void* p) {
    uint32_t a;
    asm("{ .reg .u64 t; cvta.to.shared.u64 t, %1; cvt.u32.u64 %0, t; }" : "=r"(a) : "l"(p));
    return a;
}

__device__ __forceinline__ void mma_tf32(float c[4], const uint32_t a[4], const uint32_t b[2]) {
    asm volatile(
        "mma.sync.aligned.m16n8k8.row.col.f32.tf32.tf32.f32 "
        "{%0,%1,%2,%3}, {%4,%5,%6,%7}, {%8,%9}, {%0,%1,%2,%3};"
        : "+f"(c[0]), "+f"(c[1]), "+f"(c[2]), "+f"(c[3])
        : "r"(a[0]), "r"(a[1]), "r"(a[2]), "r"(a[3]), "r"(b[0]), "r"(b[1]));
}

// ------------------------------------------------------------- prep
// Rounds weights to tf32 and resets the persistent-queue state.
__global__ void prep_kernel(const float* __restrict__ w1, const float* __restrict__ w2) {
    if (blockIdx.x == 0) {
        if (threadIdx.x == 0) g_ctr = 0;
        if (threadIdx.x < 256) g_flags[threadIdx.x] = 0;
    }
    const int n = 4 * 192 * 1024;   // == 4*1024*192
    for (int i = blockIdx.x * blockDim.x + threadIdx.x; i < n; i += gridDim.x * blockDim.x) {
        g_w1r[i] = __uint_as_float(f2tf32(w1[i]));
        g_w2r[i] = __uint_as_float(f2tf32(w2[i]));
    }
}

// ---------------------------------------------------------------------------
// Per-stage smem budgets (u32 words) inside one shared dynamic region:
// s1 stage: A 64*36=2304 + B 192*36=6912 = 9216 ; 4 stages = 36864 w
// s2 stage: A 128*36=4608 + B 256*36=9216 = 13824; 4 stages = 55296 w (max)
// ---------------------------------------------------------------------------
#define S1_STW   9216
#define S1_AW    2304
#define S2_STW   13824
#define S2_AW    4608
#define SMEM_BYTES (4 * S2_STW * 4)    // 221184 B

// --------------------------- stage-1 tile: 64x192, K=1024 (32 chunks) ------
__device__ __forceinline__ void s1_tile(uint32_t* smu, const float* __restrict__ x,
                                        int mblk, int kb)
{
    const uint32_t sb = smem_u32(smu);
    const int tid = threadIdx.x, wid = tid >> 5, lane = tid & 31;
    const int wm = wid >> 2, wn = wid & 3;       // 2 x 4
    const int lr = lane >> 2, lc = lane & 3;
    const size_t m0 = (size_t)mblk * 64;

    const float* xA = x + m0 * IN_F + (size_t)kb * 1024;
    const float* wB = g_w1r + (size_t)kb * 192 * 1024;

    auto cpA = [&](int kc, int s) {
        const float* src = xA + kc * 32;
        const uint32_t dst = sb + (uint32_t)(s * S1_STW) * 4;
#pragma unroll
        for (int i = 0; i < 2; i++) {
            int idx = i * 256 + tid, row = idx >> 3, c4 = idx & 7;
            CP16(dst + (uint32_t)(row * SSTR + c4 * 4) * 4, src + (size_t)row * IN_F + c4 * 4);
        }
    };
    auto cpB = [&](int kc, int s) {
        const float* src = wB + kc * 32;
        const uint32_t dst = sb + (uint32_t)(s * S1_STW + S1_AW) * 4;
#pragma unroll
        for (int i = 0; i < 6; i++) {
            int idx = i * 256 + tid, row = idx >> 3, c4 = idx & 7;
            CP16(dst + (uint32_t)(row * SSTR + c4 * 4) * 4, src + (size_t)row * 1024 + c4 * 4);
        }
    };

    float c[2][6][4];
#pragma unroll
    for (int mi = 0; mi < 2; mi++)
#pragma unroll
        for (int ni = 0; ni < 6; ni++)
#pragma unroll
            for (int e = 0; e < 4; e++) c[mi][ni][e] = 0.f;

    cpA(0, 0); cpB(0, 0); CPCOMMIT();
    cpA(1, 1); cpB(1, 1); CPCOMMIT();

#pragma unroll 1
    for (int kc = 0; kc < 32; kc++) {
        if (kc + 2 < 32) {
            cpA(kc + 2, (kc + 2) & 3); cpB(kc + 2, (kc + 2) & 3); CPCOMMIT();
            CPWAIT(2);
        } else if (kc + 2 == 32) {
            CPWAIT(1);
        } else {
            CPWAIT(0);
        }
        __syncthreads();

        const uint32_t* As = smu + (kc & 3) * S1_STW;
        const uint32_t* Bs = As + S1_AW;
#pragma unroll
        for (int kk = 0; kk < 4; kk++) {
            const int cc = kk * 8 + lc;
            uint32_t a[2][4], b[6][2];
#pragma unroll
            for (int mi = 0; mi < 2; mi++) {
                int r = wm * 32 + mi * 16 + lr;
                a[mi][0] = f2tf32(__uint_as_float(As[r * SSTR + cc]));
                a[mi][1] = f2tf32(__uint_as_float(As[(r + 8) * SSTR + cc]));
                a[mi][2] = f2tf32(__uint_as_float(As[r * SSTR + cc + 4]));
                a[mi][3] = f2tf32(__uint_as_float(As[(r + 8) * SSTR + cc + 4]));
            }
#pragma unroll
            for (int ni = 0; ni < 6; ni++) {
                int n = wn * 48 + ni * 8 + lr;
                b[ni][0] = Bs[n * SSTR + cc];        // pre-rounded, no cvt
                b[ni][1] = Bs[n * SSTR + cc + 4];
            }
#pragma unroll
            for (int mi = 0; mi < 2; mi++)
#pragma unroll
                for (int ni = 0; ni < 6; ni++)
                    mma_tf32(c[mi][ni], a[mi], b[ni]);
        }
    }

    // Epilogue: tf32-round, fused block transpose, 192B-run coalesced writes.
#pragma unroll
    for (int mi = 0; mi < 2; mi++) {
        int row0 = wm * 32 + mi * 16 + lr;
        size_t g0 = ((m0 + row0) * 4 + wn) * 192 + (size_t)kb * 48 + 2 * lc;
#pragma unroll
        for (int ni = 0; ni < 6; ni++) {
            float2 v0 = {__uint_as_float(f2tf32(c[mi][ni][0])),
                         __uint_as_float(f2tf32(c[mi][ni][1]))};
            float2 v1 = {__uint_as_float(f2tf32(c[mi][ni][2])),
                         __uint_as_float(f2tf32(c[mi][ni][3]))};
            *(float2*)(g_scratch + g0 + ni * 8) = v0;                        // row0
            *(float2*)(g_scratch + g0 + ni * 8 + (size_t)8 * 4 * 192) = v1;  // row0+8
        }
    }

    // Publish: all stores fenced, then one flag increment.
    __threadfence();
    __syncthreads();
    if (tid == 0) atomicAdd(&g_flags[mblk], 1);
}

// --------------------------- stage-2 tile: 128x256, K=192 (6 chunks) -------
__device__ __forceinline__ void s2_tile(uint32_t* smu, const float* __restrict__ bias,
                                        float* __restrict__ out, int u)
{
    const uint32_t sb = smem_u32(smu);
    const int tid = threadIdx.x, wid = tid >> 5, lane = tid & 31;
    const int wm = wid >> 2, wn = wid & 3;       // 2 x 4
    const int lr = lane >> 2, lc = lane & 3;
    const int nblk = u & 3, lb = (u >> 2) & 3, mblk = u >> 4;
    const size_t m0 = (size_t)mblk * 128;

    // Wait for both 64-row source blocks (all 4 kb each).
    if (tid == 0) {
        while (atomicAdd(&g_flags[2 * mblk], 0) < 4 ||
               atomicAdd(&g_flags[2 * mblk + 1], 0) < 4)
            __nanosleep(200);
    }
    __syncthreads();
    __threadfence();

    const float* Ag = g_scratch + (m0 * 4 + lb) * 192;
    const float* Bg = g_w2r + ((size_t)lb * 1024 + (size_t)nblk * 256) * 192;

    auto cpA = [&](int kc, int s) {
        const float* src = Ag + kc * 32;
        const uint32_t dst = sb + (uint32_t)(s * S2_STW) * 4;
#pragma unroll
        for (int i = 0; i < 4; i++) {
            int idx = i * 256 + tid, row = idx >> 3, c4 = idx & 7;
            CP16(dst + (uint32_t)(row * SSTR + c4 * 4) * 4, src + (size_t)row * (4 * 192) + c4 * 4);
        }
    };
    auto cpB = [&](int kc, int s) {
        const float* src = Bg + kc * 32;
        const uint32_t dst = sb + (uint32_t)(s * S2_STW + S2_AW) * 4;
#pragma unroll
        for (int i = 0; i < 8; i++) {
            int idx = i * 256 + tid, row = idx >> 3, c4 = idx & 7;
            CP16(dst + (uint32_t)(row * SSTR + c4 * 4) * 4, src + (size_t)row * 192 + c4 * 4);
        }
    };

    float c[4][8][4];
#pragma unroll
    for (int mi = 0; mi < 4; mi++)
#pragma unroll
        for (int ni = 0; ni < 8; ni++)
#pragma unroll
            for (int e = 0; e < 4; e++) c[mi][ni][e] = 0.f;

    cpA(0, 0); cpB(0, 0); CPCOMMIT();
    cpA(1, 1); cpB(1, 1); CPCOMMIT();

#pragma unroll 1
    for (int kc = 0; kc < 6; kc++) {
        if (kc + 2 < 6) {
            cpA(kc + 2, (kc + 2) & 3); cpB(kc + 2, (kc + 2) & 3); CPCOMMIT();
            CPWAIT(2);
        } else if (kc + 2 == 6) {
            CPWAIT(1);
        } else {
            CPWAIT(0);
        }
        __syncthreads();

        const uint32_t* As = smu + (kc & 3) * S2_STW;
        const uint32_t* Bs = As + S2_AW;
#pragma unroll
        for (int kk = 0; kk < 4; kk++) {
            const int cc = kk * 8 + lc;
            uint32_t a[4][4], b[8][2];
#pragma unroll
            for (int mi = 0; mi < 4; mi++) {
                int r = wm * 64 + mi * 16 + lr;
                a[mi][0] = As[r * SSTR + cc];
                a[mi][1] = As[(r + 8) * SSTR + cc];
                a[mi][2] = As[r * SSTR + cc + 4];
                a[mi][3] = As[(r + 8) * SSTR + cc + 4];
            }
#pragma unroll
            for (int ni = 0; ni < 8; ni++) {
                int n = wn * 64 + ni * 8 + lr;
                b[ni][0] = Bs[n * SSTR + cc];
                b[ni][1] = Bs[n * SSTR + cc + 4];
            }
#pragma unroll
            for (int mi = 0; mi < 4; mi++)
#pragma unroll
                for (int ni = 0; ni < 8; ni++)
                    mma_tf32(c[mi][ni], a[mi], b[ni]);
        }
    }

    // Epilogue: bias preload, float2 writes per row.
    const int col0 = lb * 1024 + nblk * 256 + wn * 64 + 2 * lc;
    float2 bs[8];
#pragma unroll
    for (int ni = 0; ni < 8; ni++)
        bs[ni] = *(const float2*)(bias + col0 + ni * 8);

#pragma unroll
    for (int mi = 0; mi < 4; mi++) {
        int row0 = wm * 64 + mi * 16 + lr;
        float* o0 = out + (m0 + row0) * OUT_F + col0;
#pragma unroll
        for (int ni = 0; ni < 8; ni++) {
            float2 v0 = {c[mi][ni][0] + bs[ni].x, c[mi][ni][1] + bs[ni].y};
            float2 v1 = {c[mi][ni][2] + bs[ni].x, c[mi][ni][3] + bs[ni].y};
            *(float2*)(o0 + ni * 8) = v0;
            *(float2*)(o0 + ni * 8 + (size_t)8 * OUT_F) = v1;
        }
    }
}

// --------------------------- persistent fused kernel -----------------------
__global__ void __launch_bounds__(256, 1)
fused_kernel(const float* __restrict__ x, const float* __restrict__ bias,
             float* __restrict__ out)
{
    extern __shared__ uint32_t smu[];
    __shared__ int s_tile;

    for (;;) {
        __syncthreads();                 // smem safe for reuse across tiles
        if (threadIdx.x == 0) s_tile = atomicAdd(&g_ctr, 1);
        __syncthreads();
        const int t = s_tile;
        if (t >= TOT_TILES) return;
        if (t < S1_TILES) {
            // mblk-major: all 4 kb of a block adjacent -> flags complete in order
            s1_tile(smu, x, t >> 2, t & 3);
        } else {
            s2_tile(smu, bias, out, t - S1_TILES);
        }
    }
}

// ---------------------------------------------------------------------------
extern "C" void kernel_launch(void* const* d_in, const int* in_sizes, int n_in,
                              void* d_out, int out_size)
{
    const float* x    = (const float*)d_in[0];
    const float* w1   = (const float*)d_in[1];
    const float* w2   = (const float*)d_in[2];
    const float* bias = (const float*)d_in[3];
    float* out = (float*)d_out;

    cudaFuncSetAttribute(fused_kernel, cudaFuncAttributeMaxDynamicSharedMemorySize, SMEM_BYTES);

    int nsm = 148;
    cudaDeviceGetAttribute(&nsm, cudaDevAttrMultiProcessorCount, 0);

    prep_kernel<<<384, 256>>>(w1, w2);
    fused_kernel<<<nsm, 256, SMEM_BYTES>>>(x, bias, out);
}